// round 5
// baseline (speedup 1.0000x reference)
#include <cuda_runtime.h>
#include <cuda_bf16.h>
#include <cstdint>

// Problem shape (fixed):
//   x[1,512,4096] fp32, W[4096,4096] fp32, A[4096,4], B[4,4096],
//   zc_w, zc_b scalars, bias[4096]; out[1,512,4096] fp32.
//
// y[s,o] = sum_i x[s,i]*W[o,i]
//        + 8*zc_w * sum_k A[o,k] * r[s,k]   (r[s,k] = sum_i B[k,i]*x[s,i])
//        + zc_b * xs[s]                      (xs[s] = sum_i x[s,i])
//        + bias[o]
//
// Heavy GEMM done in bf16x3 split on tensor cores (mma.sync m16n8k16):
//   x = xh + xl, W = wh + wl;  x*W ~= xh*wh + xh*wl + xl*wh  (fp32 accum)

#define M_DIM 512
#define N_DIM 4096
#define K_DIM 4096
#define RANK 4

#define BM 128
#define BN 64
#define KC 32          // K chunk resident in smem
#define LDA 40         // padded row stride in bf16 elems (80B rows: 16B-aligned, conflict-free frags)
#define NTHREADS 256   // 8 warps: 2 (M) x 4 (N), warp tile 64x16

// ---- scratch (__device__ globals; no runtime allocation allowed) ----
__device__ __nv_bfloat16 g_Wh[(size_t)N_DIM * K_DIM];
__device__ __nv_bfloat16 g_Wl[(size_t)N_DIM * K_DIM];
__device__ __nv_bfloat16 g_xh[(size_t)M_DIM * K_DIM];
__device__ __nv_bfloat16 g_xl[(size_t)M_DIM * K_DIM];
__device__ float g_r[M_DIM * RANK];
__device__ float g_xs[M_DIM];

// ---------------------------------------------------------------------------
// fp32 -> (bf16 hi, bf16 lo) split conversion, 4 elems/thread
// ---------------------------------------------------------------------------
__device__ __forceinline__ void split4(const float4 v, uint2& hi, uint2& lo) {
    __nv_bfloat16 h[4], l[4];
    float f[4] = {v.x, v.y, v.z, v.w};
    #pragma unroll
    for (int i = 0; i < 4; i++) {
        h[i] = __float2bfloat16(f[i]);
        l[i] = __float2bfloat16(f[i] - __bfloat162float(h[i]));
    }
    ushort4 uh, ul;
    uh.x = *(unsigned short*)&h[0]; uh.y = *(unsigned short*)&h[1];
    uh.z = *(unsigned short*)&h[2]; uh.w = *(unsigned short*)&h[3];
    ul.x = *(unsigned short*)&l[0]; ul.y = *(unsigned short*)&l[1];
    ul.z = *(unsigned short*)&l[2]; ul.w = *(unsigned short*)&l[3];
    hi = *(uint2*)&uh; lo = *(uint2*)&ul;
}

__global__ void convert_W_kernel(const float* __restrict__ src) {
    const size_t i = ((size_t)blockIdx.x * blockDim.x + threadIdx.x) * 4;
    float4 v = *reinterpret_cast<const float4*>(src + i);
    uint2 hi, lo;
    split4(v, hi, lo);
    *reinterpret_cast<uint2*>(g_Wh + i) = hi;
    *reinterpret_cast<uint2*>(g_Wl + i) = lo;
}

__global__ void convert_x_kernel(const float* __restrict__ src) {
    const size_t i = ((size_t)blockIdx.x * blockDim.x + threadIdx.x) * 4;
    float4 v = *reinterpret_cast<const float4*>(src + i);
    uint2 hi, lo;
    split4(v, hi, lo);
    *reinterpret_cast<uint2*>(g_xh + i) = hi;
    *reinterpret_cast<uint2*>(g_xl + i) = lo;
}

// ---------------------------------------------------------------------------
// rank-4 projections r[s,k] = x[s].B[k] and row sums xs[s] (fp32, exact)
// ---------------------------------------------------------------------------
__global__ void rowstats_kernel(const float* __restrict__ x,
                                const float* __restrict__ Bm) {
    const int s = blockIdx.x;
    const float* xr = x + (size_t)s * K_DIM;
    float a0 = 0.f, a1 = 0.f, a2 = 0.f, a3 = 0.f, asum = 0.f;
    for (int i = threadIdx.x; i < K_DIM; i += blockDim.x) {
        const float xv = xr[i];
        asum += xv;
        a0 += xv * Bm[0 * K_DIM + i];
        a1 += xv * Bm[1 * K_DIM + i];
        a2 += xv * Bm[2 * K_DIM + i];
        a3 += xv * Bm[3 * K_DIM + i];
    }
    #pragma unroll
    for (int off = 16; off > 0; off >>= 1) {
        a0   += __shfl_down_sync(0xFFFFFFFFu, a0, off);
        a1   += __shfl_down_sync(0xFFFFFFFFu, a1, off);
        a2   += __shfl_down_sync(0xFFFFFFFFu, a2, off);
        a3   += __shfl_down_sync(0xFFFFFFFFu, a3, off);
        asum += __shfl_down_sync(0xFFFFFFFFu, asum, off);
    }
    __shared__ float sm[8][5];
    const int w = threadIdx.x >> 5, l = threadIdx.x & 31;
    if (l == 0) { sm[w][0]=a0; sm[w][1]=a1; sm[w][2]=a2; sm[w][3]=a3; sm[w][4]=asum; }
    __syncthreads();
    if (threadIdx.x < 5) {
        float t = 0.f;
        #pragma unroll
        for (int ww = 0; ww < 8; ww++) t += sm[ww][threadIdx.x];
        if (threadIdx.x < 4) g_r[s * RANK + threadIdx.x] = t;
        else                 g_xs[s] = t;
    }
}

// ---------------------------------------------------------------------------
// mma.sync wrapper: D += A(bf16) * B(bf16), fp32 accum, m16n8k16
// ---------------------------------------------------------------------------
__device__ __forceinline__ void mma_bf16(float c[4],
                                         uint32_t a0, uint32_t a1,
                                         uint32_t a2, uint32_t a3,
                                         uint32_t b0, uint32_t b1) {
    asm volatile(
        "mma.sync.aligned.m16n8k16.row.col.f32.bf16.bf16.f32 "
        "{%0,%1,%2,%3}, {%4,%5,%6,%7}, {%8,%9}, {%0,%1,%2,%3};\n"
        : "+f"(c[0]), "+f"(c[1]), "+f"(c[2]), "+f"(c[3])
        : "r"(a0), "r"(a1), "r"(a2), "r"(a3), "r"(b0), "r"(b1));
}

// ---------------------------------------------------------------------------
// GEMM: y = x @ W^T via bf16x3, fused rank-4 + zero-conv + bias epilogue.
// CTA tile 128x64, K chunk 32, 8 warps (2x4), warp tile 64x16.
// Register prefetch of chunk kt+1 overlaps compute of chunk kt; smem is
// single-buffered so the loop carries TWO barriers (read-before-overwrite).
// ---------------------------------------------------------------------------
__global__ __launch_bounds__(NTHREADS, 2)
void gemm_kernel(const float* __restrict__ Amat,
                 const float* __restrict__ zc_w,
                 const float* __restrict__ zc_b,
                 const float* __restrict__ bias,
                 float* __restrict__ y) {
    __shared__ __nv_bfloat16 Ah[BM][LDA], Al[BM][LDA];
    __shared__ __nv_bfloat16 Bh[BN][LDA], Bl[BN][LDA];

    const int bm = blockIdx.y;       // 0..3
    const int bn = blockIdx.x;       // 0..63
    const int tid  = threadIdx.x;
    const int wid  = tid >> 5;
    const int lane = tid & 31;
    const int wm = wid >> 2;         // 0..1  -> M offset wm*64
    const int wn = wid & 3;          // 0..3  -> N offset wn*16
    const int g  = lane >> 2;        // 0..7
    const int t  = lane & 3;         // 0..3

    // global load mapping
    // A arrays: 128 rows x 4 chunks(8 bf16) = 512 uint4; 2 per thread per array
    // B arrays:  64 rows x 4 chunks         = 256 uint4; 1 per thread per array
    const int la0 = tid,        ar0 = la0 >> 2, ak0 = (la0 & 3) * 8;
    const int la1 = tid + 256,  ar1 = la1 >> 2, ak1 = (la1 & 3) * 8;
    const int br  = tid >> 2,   bk  = (tid & 3) * 8;

    const __nv_bfloat16* xh = g_xh + (size_t)(bm * BM) * K_DIM;
    const __nv_bfloat16* xl = g_xl + (size_t)(bm * BM) * K_DIM;
    const __nv_bfloat16* wh = g_Wh + (size_t)(bn * BN) * K_DIM;
    const __nv_bfloat16* wl = g_Wl + (size_t)(bn * BN) * K_DIM;

    float acc[4][2][4];   // [mt][nt][c-regs]
    #pragma unroll
    for (int i = 0; i < 4; i++)
        #pragma unroll
        for (int j = 0; j < 2; j++)
            #pragma unroll
            for (int c = 0; c < 4; c++) acc[i][j][c] = 0.f;

    uint4 pah0, pah1, pal0, pal1, pbh, pbl;

    // prefetch chunk 0
    pah0 = *reinterpret_cast<const uint4*>(xh + (size_t)ar0 * K_DIM + ak0);
    pah1 = *reinterpret_cast<const uint4*>(xh + (size_t)ar1 * K_DIM + ak1);
    pal0 = *reinterpret_cast<const uint4*>(xl + (size_t)ar0 * K_DIM + ak0);
    pal1 = *reinterpret_cast<const uint4*>(xl + (size_t)ar1 * K_DIM + ak1);
    pbh  = *reinterpret_cast<const uint4*>(wh + (size_t)br  * K_DIM + bk);
    pbl  = *reinterpret_cast<const uint4*>(wl + (size_t)br  * K_DIM + bk);

    const int NKT = K_DIM / KC;   // 128
    for (int kt = 0; kt < NKT; kt++) {
        // commit prefetched chunk kt to smem (previous readers are past the
        // trailing barrier of iteration kt-1)
        *reinterpret_cast<uint4*>(&Ah[ar0][ak0]) = pah0;
        *reinterpret_cast<uint4*>(&Ah[ar1][ak1]) = pah1;
        *reinterpret_cast<uint4*>(&Al[ar0][ak0]) = pal0;
        *reinterpret_cast<uint4*>(&Al[ar1][ak1]) = pal1;
        *reinterpret_cast<uint4*>(&Bh[br][bk])   = pbh;
        *reinterpret_cast<uint4*>(&Bl[br][bk])   = pbl;
        __syncthreads();

        // issue global prefetch for chunk kt+1 (covers DRAM latency over compute)
        if (kt + 1 < NKT) {
            const int k0 = (kt + 1) * KC;
            pah0 = *reinterpret_cast<const uint4*>(xh + (size_t)ar0 * K_DIM + k0 + ak0);
            pah1 = *reinterpret_cast<const uint4*>(xh + (size_t)ar1 * K_DIM + k0 + ak1);
            pal0 = *reinterpret_cast<const uint4*>(xl + (size_t)ar0 * K_DIM + k0 + ak0);
            pal1 = *reinterpret_cast<const uint4*>(xl + (size_t)ar1 * K_DIM + k0 + ak1);
            pbh  = *reinterpret_cast<const uint4*>(wh + (size_t)br  * K_DIM + k0 + bk);
            pbl  = *reinterpret_cast<const uint4*>(wl + (size_t)br  * K_DIM + k0 + bk);
        }

        // compute chunk kt: 2 k16 steps
        #pragma unroll
        for (int kk = 0; kk < 2; kk++) {
            const int kw = kk * 8;   // uint32 (bf16-pair) base within row

            uint32_t bh0[2], bh1[2], bl0[2], bl1[2];
            #pragma unroll
            for (int nt = 0; nt < 2; nt++) {
                const int col = wn * 16 + nt * 8 + g;
                const uint32_t* rh = reinterpret_cast<const uint32_t*>(&Bh[col][0]);
                const uint32_t* rl = reinterpret_cast<const uint32_t*>(&Bl[col][0]);
                bh0[nt] = rh[kw + t];  bh1[nt] = rh[kw + t + 4];
                bl0[nt] = rl[kw + t];  bl1[nt] = rl[kw + t + 4];
            }

            #pragma unroll
            for (int mt = 0; mt < 4; mt++) {
                const int r0 = wm * 64 + mt * 16 + g;
                const uint32_t* rh0 = reinterpret_cast<const uint32_t*>(&Ah[r0][0]);
                const uint32_t* rh8 = reinterpret_cast<const uint32_t*>(&Ah[r0 + 8][0]);
                const uint32_t* rl0 = reinterpret_cast<const uint32_t*>(&Al[r0][0]);
                const uint32_t* rl8 = reinterpret_cast<const uint32_t*>(&Al[r0 + 8][0]);
                const uint32_t ah0 = rh0[kw + t], ah1 = rh8[kw + t];
                const uint32_t ah2 = rh0[kw + t + 4], ah3 = rh8[kw + t + 4];
                const uint32_t al0 = rl0[kw + t], al1 = rl8[kw + t];
                const uint32_t al2 = rl0[kw + t + 4], al3 = rl8[kw + t + 4];
                #pragma unroll
                for (int nt = 0; nt < 2; nt++) {
                    mma_bf16(acc[mt][nt], ah0, ah1, ah2, ah3, bh0[nt], bh1[nt]); // hi*hi
                    mma_bf16(acc[mt][nt], ah0, ah1, ah2, ah3, bl0[nt], bl1[nt]); // hi*lo
                    mma_bf16(acc[mt][nt], al0, al1, al2, al3, bh0[nt], bh1[nt]); // lo*hi
                }
            }
        }
        // read-before-overwrite barrier: next iteration rewrites smem
        __syncthreads();
    }

    // fused epilogue: + 8*zc_w*(r[s].A[o]) + zc_b*xs[s] + bias[o]
    const float c1 = 8.0f * (*zc_w);
    const float zb = *zc_b;

    #pragma unroll
    for (int mt = 0; mt < 4; mt++) {
        const int s0 = bm * BM + wm * 64 + mt * 16 + g;
        const int s1 = s0 + 8;
        const float p00 = g_r[s0*RANK+0], p01 = g_r[s0*RANK+1],
                    p02 = g_r[s0*RANK+2], p03 = g_r[s0*RANK+3];
        const float p10 = g_r[s1*RANK+0], p11 = g_r[s1*RANK+1],
                    p12 = g_r[s1*RANK+2], p13 = g_r[s1*RANK+3];
        const float z0 = zb * g_xs[s0], z1 = zb * g_xs[s1];
        #pragma unroll
        for (int nt = 0; nt < 2; nt++) {
            const int o0 = bn * BN + wn * 16 + nt * 8 + t * 2;
            const float lora00 = p00*Amat[o0*RANK+0] + p01*Amat[o0*RANK+1]
                               + p02*Amat[o0*RANK+2] + p03*Amat[o0*RANK+3];
            const float lora01 = p00*Amat[(o0+1)*RANK+0] + p01*Amat[(o0+1)*RANK+1]
                               + p02*Amat[(o0+1)*RANK+2] + p03*Amat[(o0+1)*RANK+3];
            const float lora10 = p10*Amat[o0*RANK+0] + p11*Amat[o0*RANK+1]
                               + p12*Amat[o0*RANK+2] + p13*Amat[o0*RANK+3];
            const float lora11 = p10*Amat[(o0+1)*RANK+0] + p11*Amat[(o0+1)*RANK+1]
                               + p12*Amat[(o0+1)*RANK+2] + p13*Amat[(o0+1)*RANK+3];
            const float b0v = bias[o0], b1v = bias[o0 + 1];
            float2 v0, v1;
            v0.x = acc[mt][nt][0] + c1 * lora00 + z0 + b0v;
            v0.y = acc[mt][nt][1] + c1 * lora01 + z0 + b1v;
            v1.x = acc[mt][nt][2] + c1 * lora10 + z1 + b0v;
            v1.y = acc[mt][nt][3] + c1 * lora11 + z1 + b1v;
            *reinterpret_cast<float2*>(y + (size_t)s0 * N_DIM + o0) = v0;
            *reinterpret_cast<float2*>(y + (size_t)s1 * N_DIM + o0) = v1;
        }
    }
}

// ---------------------------------------------------------------------------
extern "C" void kernel_launch(void* const* d_in, const int* in_sizes, int n_in,
                              void* d_out, int out_size) {
    const float* x    = (const float*)d_in[0];
    const float* W    = (const float*)d_in[1];
    const float* Amat = (const float*)d_in[2];
    const float* Bmat = (const float*)d_in[3];
    const float* zc_w = (const float*)d_in[4];
    const float* zc_b = (const float*)d_in[5];
    const float* bias = (const float*)d_in[6];
    float* y = (float*)d_out;

    // fp32 -> bf16 hi/lo splits (write __device__ scratch directly)
    convert_W_kernel<<<((size_t)N_DIM * K_DIM) / (256 * 4), 256>>>(W);
    convert_x_kernel<<<((size_t)M_DIM * K_DIM) / (256 * 4), 256>>>(x);

    // exact fp32 rank-4 row projections
    rowstats_kernel<<<M_DIM, 256>>>(x, Bmat);

    dim3 grid(N_DIM / BN, M_DIM / BM);   // (64, 4) = 256 CTAs
    gemm_kernel<<<grid, NTHREADS>>>(Amat, zc_w, zc_b, bias, y);
}

// round 6
// speedup vs baseline: 1.1599x; 1.1599x over previous
#include <cuda_runtime.h>
#include <cuda_bf16.h>
#include <cstdint>

// Problem shape (fixed):
//   x[1,512,4096] fp32, W[4096,4096] fp32, A[4096,4], B[4,4096],
//   zc_w, zc_b scalars, bias[4096]; out[1,512,4096] fp32.
//
// y[s,o] = sum_i x[s,i]*W[o,i]
//        + 8*zc_w * sum_k A[o,k] * r[s,k]   (r[s,k] = sum_i B[k,i]*x[s,i])
//        + zc_b * xs[s]                      (xs[s] = sum_i x[s,i])
//        + bias[o]
//
// Heavy GEMM done in bf16x3 split on tensor cores (mma.sync m16n8k16):
//   x = xh + xl, W = wh + wl;  x*W ~= xh*wh + xh*wl + xl*wh  (fp32 accum)
// Fragment loads via ldmatrix.x4 (R5: replaces 80 scalar LDS32/chunk with 20 LDSM).

#define M_DIM 512
#define N_DIM 4096
#define K_DIM 4096
#define RANK 4

#define BM 128
#define BN 64
#define KC 32          // K chunk resident in smem
#define LDA 40         // padded row stride in bf16 elems (80B rows: 16B-aligned, LDSM conflict-free)
#define NTHREADS 256   // 8 warps: 2 (M) x 4 (N), warp tile 64x16

// ---- scratch (__device__ globals; no runtime allocation allowed) ----
__device__ __nv_bfloat16 g_Wh[(size_t)N_DIM * K_DIM];
__device__ __nv_bfloat16 g_Wl[(size_t)N_DIM * K_DIM];
__device__ __nv_bfloat16 g_xh[(size_t)M_DIM * K_DIM];
__device__ __nv_bfloat16 g_xl[(size_t)M_DIM * K_DIM];
__device__ float g_r[M_DIM * RANK];
__device__ float g_xs[M_DIM];

// ---------------------------------------------------------------------------
// fp32 -> (bf16 hi, bf16 lo) split conversion, 4 elems/thread
// ---------------------------------------------------------------------------
__device__ __forceinline__ void split4(const float4 v, uint2& hi, uint2& lo) {
    __nv_bfloat16 h[4], l[4];
    float f[4] = {v.x, v.y, v.z, v.w};
    #pragma unroll
    for (int i = 0; i < 4; i++) {
        h[i] = __float2bfloat16(f[i]);
        l[i] = __float2bfloat16(f[i] - __bfloat162float(h[i]));
    }
    ushort4 uh, ul;
    uh.x = *(unsigned short*)&h[0]; uh.y = *(unsigned short*)&h[1];
    uh.z = *(unsigned short*)&h[2]; uh.w = *(unsigned short*)&h[3];
    ul.x = *(unsigned short*)&l[0]; ul.y = *(unsigned short*)&l[1];
    ul.z = *(unsigned short*)&l[2]; ul.w = *(unsigned short*)&l[3];
    hi = *(uint2*)&uh; lo = *(uint2*)&ul;
}

__global__ void convert_W_kernel(const float* __restrict__ src) {
    const size_t i = ((size_t)blockIdx.x * blockDim.x + threadIdx.x) * 4;
    float4 v = *reinterpret_cast<const float4*>(src + i);
    uint2 hi, lo;
    split4(v, hi, lo);
    *reinterpret_cast<uint2*>(g_Wh + i) = hi;
    *reinterpret_cast<uint2*>(g_Wl + i) = lo;
}

__global__ void convert_x_kernel(const float* __restrict__ src) {
    const size_t i = ((size_t)blockIdx.x * blockDim.x + threadIdx.x) * 4;
    float4 v = *reinterpret_cast<const float4*>(src + i);
    uint2 hi, lo;
    split4(v, hi, lo);
    *reinterpret_cast<uint2*>(g_xh + i) = hi;
    *reinterpret_cast<uint2*>(g_xl + i) = lo;
}

// ---------------------------------------------------------------------------
// rank-4 projections r[s,k] = x[s].B[k] and row sums xs[s] (fp32, exact)
// ---------------------------------------------------------------------------
__global__ void rowstats_kernel(const float* __restrict__ x,
                                const float* __restrict__ Bm) {
    const int s = blockIdx.x;
    const float* xr = x + (size_t)s * K_DIM;
    float a0 = 0.f, a1 = 0.f, a2 = 0.f, a3 = 0.f, asum = 0.f;
    for (int i = threadIdx.x; i < K_DIM; i += blockDim.x) {
        const float xv = xr[i];
        asum += xv;
        a0 += xv * Bm[0 * K_DIM + i];
        a1 += xv * Bm[1 * K_DIM + i];
        a2 += xv * Bm[2 * K_DIM + i];
        a3 += xv * Bm[3 * K_DIM + i];
    }
    #pragma unroll
    for (int off = 16; off > 0; off >>= 1) {
        a0   += __shfl_down_sync(0xFFFFFFFFu, a0, off);
        a1   += __shfl_down_sync(0xFFFFFFFFu, a1, off);
        a2   += __shfl_down_sync(0xFFFFFFFFu, a2, off);
        a3   += __shfl_down_sync(0xFFFFFFFFu, a3, off);
        asum += __shfl_down_sync(0xFFFFFFFFu, asum, off);
    }
    __shared__ float sm[8][5];
    const int w = threadIdx.x >> 5, l = threadIdx.x & 31;
    if (l == 0) { sm[w][0]=a0; sm[w][1]=a1; sm[w][2]=a2; sm[w][3]=a3; sm[w][4]=asum; }
    __syncthreads();
    if (threadIdx.x < 5) {
        float t = 0.f;
        #pragma unroll
        for (int ww = 0; ww < 8; ww++) t += sm[ww][threadIdx.x];
        if (threadIdx.x < 4) g_r[s * RANK + threadIdx.x] = t;
        else                 g_xs[s] = t;
    }
}

// ---------------------------------------------------------------------------
// mma.sync + ldmatrix wrappers
// ---------------------------------------------------------------------------
__device__ __forceinline__ void mma_bf16(float c[4],
                                         uint32_t a0, uint32_t a1,
                                         uint32_t a2, uint32_t a3,
                                         uint32_t b0, uint32_t b1) {
    asm volatile(
        "mma.sync.aligned.m16n8k16.row.col.f32.bf16.bf16.f32 "
        "{%0,%1,%2,%3}, {%4,%5,%6,%7}, {%8,%9}, {%0,%1,%2,%3};\n"
        : "+f"(c[0]), "+f"(c[1]), "+f"(c[2]), "+f"(c[3])
        : "r"(a0), "r"(a1), "r"(a2), "r"(a3), "r"(b0), "r"(b1));
}

__device__ __forceinline__ void ldsm_x4(uint32_t& r0, uint32_t& r1,
                                        uint32_t& r2, uint32_t& r3,
                                        uint32_t saddr) {
    asm volatile(
        "ldmatrix.sync.aligned.m8n8.x4.shared.b16 {%0,%1,%2,%3}, [%4];\n"
        : "=r"(r0), "=r"(r1), "=r"(r2), "=r"(r3) : "r"(saddr));
}

// ---------------------------------------------------------------------------
// GEMM: y = x @ W^T via bf16x3, fused rank-4 + zero-conv + bias epilogue.
// CTA tile 128x64, K chunk 32, 8 warps (2x4), warp tile 64x16.
// Register prefetch of chunk kt+1 overlaps compute of chunk kt; smem is
// single-buffered so the loop carries TWO barriers (read-before-overwrite).
// Fragments loaded with ldmatrix.x4.
// ---------------------------------------------------------------------------
__global__ __launch_bounds__(NTHREADS, 2)
void gemm_kernel(const float* __restrict__ Amat,
                 const float* __restrict__ zc_w,
                 const float* __restrict__ zc_b,
                 const float* __restrict__ bias,
                 float* __restrict__ y) {
    __shared__ __nv_bfloat16 Ah[BM][LDA], Al[BM][LDA];
    __shared__ __nv_bfloat16 Bh[BN][LDA], Bl[BN][LDA];

    const int bm = blockIdx.y;       // 0..3
    const int bn = blockIdx.x;       // 0..63
    const int tid  = threadIdx.x;
    const int wid  = tid >> 5;
    const int lane = tid & 31;
    const int wm = wid >> 2;         // 0..1  -> M offset wm*64
    const int wn = wid & 3;          // 0..3  -> N offset wn*16
    const int g  = lane >> 2;        // 0..7  (epilogue row group)
    const int t  = lane & 3;         // 0..3  (epilogue col group)

    // ldmatrix per-lane source mapping
    // A (x4): quads = {rows0-7 kLo, rows8-15 kLo, rows0-7 kHi, rows8-15 kHi}
    const int lrowA = (lane & 7) + ((lane >> 3) & 1) * 8;   // 0..15
    const int lkbA  = (lane >> 4) * 16;                     // 0 or 16 bytes
    // B (x4): quads = {n0-7 kLo, n0-7 kHi, n8-15 kLo, n8-15 kHi}
    const int lcolB = wn * 16 + (lane & 7) + ((lane >> 4) & 1) * 8;
    const int lkbB  = ((lane >> 3) & 1) * 16;               // 0 or 16 bytes

    uint32_t aHiBase[4], aLoBase[4];
    #pragma unroll
    for (int mt = 0; mt < 4; mt++) {
        const int r = wm * 64 + mt * 16 + lrowA;
        aHiBase[mt] = (uint32_t)__cvta_generic_to_shared(&Ah[r][0]) + lkbA;
        aLoBase[mt] = (uint32_t)__cvta_generic_to_shared(&Al[r][0]) + lkbA;
    }
    const uint32_t bHiBase = (uint32_t)__cvta_generic_to_shared(&Bh[lcolB][0]) + lkbB;
    const uint32_t bLoBase = (uint32_t)__cvta_generic_to_shared(&Bl[lcolB][0]) + lkbB;

    // global load mapping
    // A arrays: 128 rows x 4 chunks(8 bf16) = 512 uint4; 2 per thread per array
    // B arrays:  64 rows x 4 chunks         = 256 uint4; 1 per thread per array
    const int la0 = tid,        ar0 = la0 >> 2, ak0 = (la0 & 3) * 8;
    const int la1 = tid + 256,  ar1 = la1 >> 2, ak1 = (la1 & 3) * 8;
    const int br  = tid >> 2,   bk  = (tid & 3) * 8;

    const __nv_bfloat16* xh = g_xh + (size_t)(bm * BM) * K_DIM;
    const __nv_bfloat16* xl = g_xl + (size_t)(bm * BM) * K_DIM;
    const __nv_bfloat16* wh = g_Wh + (size_t)(bn * BN) * K_DIM;
    const __nv_bfloat16* wl = g_Wl + (size_t)(bn * BN) * K_DIM;

    float acc[4][2][4];   // [mt][nt][c-regs]
    #pragma unroll
    for (int i = 0; i < 4; i++)
        #pragma unroll
        for (int j = 0; j < 2; j++)
            #pragma unroll
            for (int c = 0; c < 4; c++) acc[i][j][c] = 0.f;

    uint4 pah0, pah1, pal0, pal1, pbh, pbl;

    // prefetch chunk 0
    pah0 = *reinterpret_cast<const uint4*>(xh + (size_t)ar0 * K_DIM + ak0);
    pah1 = *reinterpret_cast<const uint4*>(xh + (size_t)ar1 * K_DIM + ak1);
    pal0 = *reinterpret_cast<const uint4*>(xl + (size_t)ar0 * K_DIM + ak0);
    pal1 = *reinterpret_cast<const uint4*>(xl + (size_t)ar1 * K_DIM + ak1);
    pbh  = *reinterpret_cast<const uint4*>(wh + (size_t)br  * K_DIM + bk);
    pbl  = *reinterpret_cast<const uint4*>(wl + (size_t)br  * K_DIM + bk);

    const int NKT = K_DIM / KC;   // 128
    for (int kt = 0; kt < NKT; kt++) {
        // commit prefetched chunk kt to smem
        *reinterpret_cast<uint4*>(&Ah[ar0][ak0]) = pah0;
        *reinterpret_cast<uint4*>(&Ah[ar1][ak1]) = pah1;
        *reinterpret_cast<uint4*>(&Al[ar0][ak0]) = pal0;
        *reinterpret_cast<uint4*>(&Al[ar1][ak1]) = pal1;
        *reinterpret_cast<uint4*>(&Bh[br][bk])   = pbh;
        *reinterpret_cast<uint4*>(&Bl[br][bk])   = pbl;
        __syncthreads();

        // issue global prefetch for chunk kt+1 (covers DRAM latency over compute)
        if (kt + 1 < NKT) {
            const int k0 = (kt + 1) * KC;
            pah0 = *reinterpret_cast<const uint4*>(xh + (size_t)ar0 * K_DIM + k0 + ak0);
            pah1 = *reinterpret_cast<const uint4*>(xh + (size_t)ar1 * K_DIM + k0 + ak1);
            pal0 = *reinterpret_cast<const uint4*>(xl + (size_t)ar0 * K_DIM + k0 + ak0);
            pal1 = *reinterpret_cast<const uint4*>(xl + (size_t)ar1 * K_DIM + k0 + ak1);
            pbh  = *reinterpret_cast<const uint4*>(wh + (size_t)br  * K_DIM + k0 + bk);
            pbl  = *reinterpret_cast<const uint4*>(wl + (size_t)br  * K_DIM + k0 + bk);
        }

        // compute chunk kt: 2 k16 steps
        #pragma unroll
        for (int kk = 0; kk < 2; kk++) {
            const int kb = kk * 32;   // byte offset of this k16 step within the row

            // B fragments: one x4 covers both n-tiles (hi), one covers lo
            uint32_t bh0[2], bh1[2], bl0[2], bl1[2];
            ldsm_x4(bh0[0], bh1[0], bh0[1], bh1[1], bHiBase + kb);
            ldsm_x4(bl0[0], bl1[0], bl0[1], bl1[1], bLoBase + kb);

            #pragma unroll
            for (int mt = 0; mt < 4; mt++) {
                uint32_t ah0, ah1, ah2, ah3, al0, al1, al2, al3;
                ldsm_x4(ah0, ah1, ah2, ah3, aHiBase[mt] + kb);
                ldsm_x4(al0, al1, al2, al3, aLoBase[mt] + kb);
                #pragma unroll
                for (int nt = 0; nt < 2; nt++) {
                    mma_bf16(acc[mt][nt], ah0, ah1, ah2, ah3, bh0[nt], bh1[nt]); // hi*hi
                    mma_bf16(acc[mt][nt], ah0, ah1, ah2, ah3, bl0[nt], bl1[nt]); // hi*lo
                    mma_bf16(acc[mt][nt], al0, al1, al2, al3, bh0[nt], bh1[nt]); // lo*hi
                }
            }
        }
        // read-before-overwrite barrier: next iteration rewrites smem
        __syncthreads();
    }

    // fused epilogue: + 8*zc_w*(r[s].A[o]) + zc_b*xs[s] + bias[o]
    const float c1 = 8.0f * (*zc_w);
    const float zb = *zc_b;

    #pragma unroll
    for (int mt = 0; mt < 4; mt++) {
        const int s0 = bm * BM + wm * 64 + mt * 16 + g;
        const int s1 = s0 + 8;
        const float p00 = g_r[s0*RANK+0], p01 = g_r[s0*RANK+1],
                    p02 = g_r[s0*RANK+2], p03 = g_r[s0*RANK+3];
        const float p10 = g_r[s1*RANK+0], p11 = g_r[s1*RANK+1],
                    p12 = g_r[s1*RANK+2], p13 = g_r[s1*RANK+3];
        const float z0 = zb * g_xs[s0], z1 = zb * g_xs[s1];
        #pragma unroll
        for (int nt = 0; nt < 2; nt++) {
            const int o0 = bn * BN + wn * 16 + nt * 8 + t * 2;
            const float lora00 = p00*Amat[o0*RANK+0] + p01*Amat[o0*RANK+1]
                               + p02*Amat[o0*RANK+2] + p03*Amat[o0*RANK+3];
            const float lora01 = p00*Amat[(o0+1)*RANK+0] + p01*Amat[(o0+1)*RANK+1]
                               + p02*Amat[(o0+1)*RANK+2] + p03*Amat[(o0+1)*RANK+3];
            const float lora10 = p10*Amat[o0*RANK+0] + p11*Amat[o0*RANK+1]
                               + p12*Amat[o0*RANK+2] + p13*Amat[o0*RANK+3];
            const float lora11 = p10*Amat[(o0+1)*RANK+0] + p11*Amat[(o0+1)*RANK+1]
                               + p12*Amat[(o0+1)*RANK+2] + p13*Amat[(o0+1)*RANK+3];
            const float b0v = bias[o0], b1v = bias[o0 + 1];
            float2 v0, v1;
            v0.x = acc[mt][nt][0] + c1 * lora00 + z0 + b0v;
            v0.y = acc[mt][nt][1] + c1 * lora01 + z0 + b1v;
            v1.x = acc[mt][nt][2] + c1 * lora10 + z1 + b0v;
            v1.y = acc[mt][nt][3] + c1 * lora11 + z1 + b1v;
            *reinterpret_cast<float2*>(y + (size_t)s0 * N_DIM + o0) = v0;
            *reinterpret_cast<float2*>(y + (size_t)s1 * N_DIM + o0) = v1;
        }
    }
}

// ---------------------------------------------------------------------------
extern "C" void kernel_launch(void* const* d_in, const int* in_sizes, int n_in,
                              void* d_out, int out_size) {
    const float* x    = (const float*)d_in[0];
    const float* W    = (const float*)d_in[1];
    const float* Amat = (const float*)d_in[2];
    const float* Bmat = (const float*)d_in[3];
    const float* zc_w = (const float*)d_in[4];
    const float* zc_b = (const float*)d_in[5];
    const float* bias = (const float*)d_in[6];
    float* y = (float*)d_out;

    // fp32 -> bf16 hi/lo splits (write __device__ scratch directly)
    convert_W_kernel<<<((size_t)N_DIM * K_DIM) / (256 * 4), 256>>>(W);
    convert_x_kernel<<<((size_t)M_DIM * K_DIM) / (256 * 4), 256>>>(x);

    // exact fp32 rank-4 row projections
    rowstats_kernel<<<M_DIM, 256>>>(x, Bmat);

    dim3 grid(N_DIM / BN, M_DIM / BM);   // (64, 4) = 256 CTAs
    gemm_kernel<<<grid, NTHREADS>>>(Amat, zc_w, zc_b, bias, y);
}